// round 5
// baseline (speedup 1.0000x reference)
#include <cuda_runtime.h>
#include <math.h>

// Problem constants
#define GH 52
#define GW 52
#define GRID_CELLS (GH * GW)            // 2704
#define NA 9
#define NB 256
#define N_ELEM (NB * GRID_CELLS * NA)   // 6,230,016
#define TILE_ELEMS 1024
#define TILE_FLOATS (TILE_ELEMS * 5)    // 5120 floats
#define TILE_BYTES (TILE_FLOATS * 4)    // 20480 bytes
#define NUM_TILES (N_ELEM / TILE_ELEMS) // 6084 exactly
#define THREADS 256
#define DEPTH 3
#define NBLOCKS 456                     // 3 blocks/SM * 152 SMs (62KB smem/block)

__device__ float2 g_partials[NBLOCKS];
__device__ unsigned int g_count = 0;

__device__ __forceinline__ float tanh_approx(float x) {
    float y;
    asm("tanh.approx.f32 %0, %1;" : "=f"(y) : "f"(x));
    return y;
}

__device__ __forceinline__ float warp_reduce(float v) {
#pragma unroll
    for (int o = 16; o > 0; o >>= 1)
        v += __shfl_down_sync(0xFFFFFFFFu, v, o);
    return v;
}

__device__ __forceinline__ unsigned smem_u32(const void* p) {
    return (unsigned)__cvta_generic_to_shared(p);
}

__device__ __forceinline__ void mbar_init(unsigned mbar, unsigned count) {
    asm volatile("mbarrier.init.shared.b64 [%0], %1;" :: "r"(mbar), "r"(count) : "memory");
}

// L2 persistence policy: keep the streamed tensor resident across graph replays
__device__ __forceinline__ unsigned long long evict_last_policy() {
    unsigned long long pol;
    asm("createpolicy.fractional.L2::evict_last.b64 %0, 1.0;" : "=l"(pol));
    return pol;
}

// expect_tx + TMA bulk copy global->shared with L2 cache hint, completion on mbarrier
__device__ __forceinline__ void bulk_ld(unsigned dst, const void* src,
                                        unsigned bytes, unsigned mbar,
                                        unsigned long long pol) {
    asm volatile("mbarrier.arrive.expect_tx.shared.b64 _, [%0], %1;"
                 :: "r"(mbar), "r"(bytes) : "memory");
    asm volatile("cp.async.bulk.shared::cluster.global.mbarrier::complete_tx::bytes"
                 ".L2::cache_hint [%0], [%1], %2, [%3], %4;"
                 :: "r"(dst), "l"(src), "r"(bytes), "r"(mbar), "l"(pol) : "memory");
}

__device__ __forceinline__ void mbar_wait(unsigned mbar, unsigned phase) {
    asm volatile(
        "{\n\t"
        ".reg .pred P;\n\t"
        "WAIT_%=:\n\t"
        "mbarrier.try_wait.parity.acquire.cta.shared::cta.b64 P, [%0], %1;\n\t"
        "@!P bra WAIT_%=;\n\t"
        "}"
        :: "r"(mbar), "r"(phase) : "memory");
}

__global__ void __launch_bounds__(THREADS) yolo_loss_kernel(
    const float* __restrict__ pred, const float* __restrict__ label,
    const float* __restrict__ anchors, float* __restrict__ out)
{
    __shared__ __align__(128) float s_tile[DEPTH][TILE_FLOATS];   // 3 x 20KB
    __shared__ float s_anch[2 * NA];           // raw anchors (for tail)
    __shared__ float2 s_anch2[NA];             // squared anchors
    __shared__ float s_red[16];
    __shared__ unsigned s_flag;
    __shared__ __align__(8) unsigned long long s_mbar[DEPTH];

    const int tid = threadIdx.x;
    const int bid = blockIdx.x;
    if (tid < 2 * NA) s_anch[tid] = anchors[tid];
    if (tid < NA) {
        const float aw = anchors[2 * tid], ah = anchors[2 * tid + 1];
        s_anch2[tid] = make_float2(aw * aw, ah * ah);
    }
    if (tid == 0) {
#pragma unroll
        for (int s = 0; s < DEPTH; s++) mbar_init(smem_u32(&s_mbar[s]), 1);
    }
    __syncthreads();

    const char* __restrict__ pbytes = (const char*)pred;
    const unsigned long long pol = evict_last_policy();

    // ---- prologue: issue up to DEPTH bulk copies ----
    if (tid == 0) {
#pragma unroll
        for (int s = 0; s < DEPTH; s++) {
            const int t = bid + s * NBLOCKS;
            if (t < NUM_TILES)
                bulk_ld(smem_u32(s_tile[s]), pbytes + (long)t * TILE_BYTES,
                        TILE_BYTES, smem_u32(&s_mbar[s]), pol);
        }
    }

    // raw accumulators (scaling deferred)
    float acc_xy = 0.0f;   // sum tanh^2 for x,y
    float acc_wh = 0.0f;   // sum a^2*(e-1)^2
    float acc_t  = 0.0f;   // sum tanh(conf/2)
    float acc_t2 = 0.0f;   // sum tanh(conf/2)^2

    // anchor index of element (t*1024 + tid): 1024%9==7 -> init (bid*7+tid)%9
    // per-tile step (t += 456): 456*1024 % 9 == 6 ; per k-chunk (+256): +4
    int a0 = (bid * 7 + tid) % 9;

    int stage = 0, phase = 0;
    for (int t = bid; t < NUM_TILES; t += NBLOCKS) {
        mbar_wait(smem_u32(&s_mbar[stage]), (unsigned)phase);

        const float* __restrict__ buf = s_tile[stage];
        int a = a0;
#pragma unroll
        for (int k = 0; k < 4; k++) {
            const int local = tid + k * THREADS;
            const float v0 = buf[5 * local + 0];
            const float v1 = buf[5 * local + 1];
            const float v2 = buf[5 * local + 2];
            const float v3 = buf[5 * local + 3];
            const float v4 = buf[5 * local + 4];
            const float2 a2 = s_anch2[a];

            const float tx = tanh_approx(0.5f * v0);
            const float ty = tanh_approx(0.5f * v1);
            acc_xy = fmaf(tx, tx, acc_xy);
            acc_xy = fmaf(ty, ty, acc_xy);

            const float ew = __expf(v2) - 1.0f;
            const float eh = __expf(v3) - 1.0f;
            acc_wh = fmaf(a2.x, ew * ew, acc_wh);
            acc_wh = fmaf(a2.y, eh * eh, acc_wh);

            const float tc = tanh_approx(0.5f * v4);
            acc_t += tc;
            acc_t2 = fmaf(tc, tc, acc_t2);

            a += 4; if (a >= 9) a -= 9;
        }

        __syncthreads();   // all threads done reading buf[stage]
        if (tid == 0) {
            const int tn = t + DEPTH * NBLOCKS;
            if (tn < NUM_TILES)
                bulk_ld(smem_u32(s_tile[stage]), pbytes + (long)tn * TILE_BYTES,
                        TILE_BYTES, smem_u32(&s_mbar[stage]), pol);
        }

        if (++stage == DEPTH) { stage = 0; phase ^= 1; }
        a0 += 6; if (a0 >= 9) a0 -= 9;
    }

    // per-thread element count for the deferred conf constant
    const int n_tiles = (bid < NUM_TILES) ? ((NUM_TILES - 1 - bid) / NBLOCKS + 1) : 0;
    const float cnt = 4.0f * (float)n_tiles;

    // fold deferred scalings:  (sig-0.5)^2 = tanh^2/4 ; /(52^2) => /10816
    float coor = acc_wh + acc_xy * (1.0f / 10816.0f);
    // sig^2 = 0.25 + 0.5 t + 0.25 t^2
    float conf = 0.25f * cnt + 0.5f * acc_t + 0.25f * acc_t2;

    // ---- block reduction ----
    coor = warp_reduce(coor);
    conf = warp_reduce(conf);
    const int wid = tid >> 5, lid = tid & 31;
    if (lid == 0) { s_red[wid] = coor; s_red[8 + wid] = conf; }
    __syncthreads();
    if (wid == 0) {
        float c = (lid < 8) ? s_red[lid] : 0.0f;
        float f = (lid < 8) ? s_red[8 + lid] : 0.0f;
        c = warp_reduce(c);
        f = warp_reduce(f);
        if (lid == 0) {
            g_partials[bid] = make_float2(c, f);
            __threadfence();
            const unsigned old = atomicAdd(&g_count, 1u);
            s_flag = (old == (unsigned)(NBLOCKS - 1)) ? 1u : 0u;
        }
    }
    __syncthreads();
    if (!s_flag) return;

    // ================= finishing block: obj terms + final combine =================
    const int b = tid;   // one sample per thread (B == THREADS == 256)

    const float lx = label[4 * b + 0];
    const float ly = label[4 * b + 1];
    const float lw = label[4 * b + 2];
    const float lh = label[4 * b + 3];

    const float fx = floorf(lx * (float)GW);
    const float fy = floorf(ly * (float)GH);
    const int idx = (int)(fx * (float)GH + fy);

    float best = -1.0f;
    int am = 0;
#pragma unroll
    for (int a = 0; a < NA; a++) {
        const float dw = lw - s_anch[2 * a];
        const float dh = lh - s_anch[2 * a + 1];
        const float d = dw * dw + dh * dh;
        if (d > best) { best = d; am = a; }   // first-max, matches argmax
    }
    const float aw = s_anch[2 * am];
    const float ah = s_anch[2 * am + 1];

    const float* p = pred + (((size_t)b * GRID_CELLS + (size_t)idx) * NA + (size_t)am) * 5;
    const float s0 = 1.0f / (1.0f + expf(-p[0]));
    const float s1 = 1.0f / (1.0f + expf(-p[1]));
    const float x = (s0 + fx) / (float)GW;
    const float y = (s1 + fy) / (float)GH;
    const float w = aw * expf(p[2]);
    const float h = ah * expf(p[3]);
    const float cf = 1.0f / (1.0f + expf(-p[4]));

    const float agx = (fx + 0.5f) / (float)GW;
    const float agy = (fy + 0.5f) / (float)GH;

    float t0 = x - agx, t1 = y - agy, t2 = w - aw, t3 = h - ah;
    const float coor_sq_obj = t0 * t0 + t1 * t1 + t2 * t2 + t3 * t3;
    const float conf_sq_obj = cf * cf;

    t0 = x - lx; t1 = y - ly; t2 = w - lw; t3 = h - lh;
    const float coor_obj = t0 * t0 + t1 * t1 + t2 * t2 + t3 * t3;

    // IoU (faithful to reference, incl. area = x2*y2 quirk)
    const float lx1 = fmaxf(lx - lw * 0.5f, 0.0f);
    const float ly1 = fmaxf(ly - lh * 0.5f, 0.0f);
    const float lx2 = fminf(lx + lw * 0.5f, 1.0f);
    const float ly2 = fminf(ly + lh * 0.5f, 1.0f);
    const float px1 = fmaxf(x - w * 0.5f, 0.0f);
    const float py1 = fmaxf(y - h * 0.5f, 0.0f);
    const float px2 = fminf(x + w * 0.5f, 1.0f);
    const float py2 = fminf(y + h * 0.5f, 1.0f);

    const float ix1 = fmaxf(lx1, px1);
    const float iy1 = fmaxf(ly1, py1);
    const float ix2 = fminf(lx2, px2);
    const float iy2 = fminf(ly2, py2);

    const float la = lx2 * ly2;
    const float pa = px2 * py2;
    const float inter = fmaxf(ix2 - ix1, 0.0f) * fmaxf(iy2 - iy1, 0.0f);
    const float iou = inter / (la + pa - inter);
    const float dcf = cf - iou;
    const float conf_obj = dcf * dcf;

    // gather all blocks' noobj partials
    double coorAll = 0.0, confAll = 0.0;
    for (int i = b; i < NBLOCKS; i += THREADS) {
        const float2 v = g_partials[i];
        coorAll += (double)v.x;
        confAll += (double)v.y;
    }

    // reduce the 6 quantities in shared (reuse tile buffer as scratch)
    double* red = (double*)s_tile;
    red[b * 6 + 0] = coorAll;
    red[b * 6 + 1] = confAll;
    red[b * 6 + 2] = (double)coor_sq_obj;
    red[b * 6 + 3] = (double)conf_sq_obj;
    red[b * 6 + 4] = (double)coor_obj;
    red[b * 6 + 5] = (double)conf_obj;
    __syncthreads();
    for (int s = THREADS / 2; s > 0; s >>= 1) {
        if (b < s) {
#pragma unroll
            for (int j = 0; j < 6; j++) red[b * 6 + j] += red[(b + s) * 6 + j];
        }
        __syncthreads();
    }

    if (b == 0) {
        const double GA1 = (double)(GRID_CELLS * NA - 1);   // 24335
        const double Bd = (double)NB;
        const double coor_l_noobj = (red[0] - red[2]) / (Bd * GA1 * 4.0);
        const double conf_l_noobj = (red[1] - red[3]) / (Bd * GA1);
        const double coor_l_obj = red[4] / (Bd * 4.0);
        const double conf_l_obj = red[5] / Bd;
        out[0] = (float)(coor_l_obj + coor_l_noobj + conf_l_obj + conf_l_noobj);
        g_count = 0;   // reset for next graph replay
    }
}

extern "C" void kernel_launch(void* const* d_in, const int* in_sizes, int n_in,
                              void* d_out, int out_size) {
    const float* pred    = (const float*)d_in[0];   // [256, 2704, 9, 5]
    const float* label   = (const float*)d_in[1];   // [256, 4]
    const float* anchors = (const float*)d_in[2];   // [9, 2]
    float* out = (float*)d_out;

    yolo_loss_kernel<<<NBLOCKS, THREADS>>>(pred, label, anchors, out);
}

// round 6
// speedup vs baseline: 1.1240x; 1.1240x over previous
#include <cuda_runtime.h>
#include <math.h>

// Problem constants
#define GH 52
#define GW 52
#define GRID_CELLS (GH * GW)            // 2704
#define NA 9
#define NB 256
#define N_ELEM (NB * GRID_CELLS * NA)   // 6,230,016
#define TILE_ELEMS 1024
#define TILE_FLOATS (TILE_ELEMS * 5)    // 5120 floats
#define TILE_BYTES (TILE_FLOATS * 4)    // 20480 bytes
#define NUM_TILES (N_ELEM / TILE_ELEMS) // 6084 exactly
#define THREADS 256
#define DEPTH 2
#define NBLOCKS 608                     // 4 blocks/SM * 152 SMs (42KB smem/block)

__device__ float2 g_partials[NBLOCKS];
__device__ float4 g_obj[NB];            // per-sample obj terms, computed by blocks 0..255
__device__ unsigned int g_count = 0;

__device__ __forceinline__ float tanh_approx(float x) {
    float y;
    asm("tanh.approx.f32 %0, %1;" : "=f"(y) : "f"(x));
    return y;
}

__device__ __forceinline__ float warp_reduce(float v) {
#pragma unroll
    for (int o = 16; o > 0; o >>= 1)
        v += __shfl_down_sync(0xFFFFFFFFu, v, o);
    return v;
}

__device__ __forceinline__ unsigned smem_u32(const void* p) {
    return (unsigned)__cvta_generic_to_shared(p);
}

__device__ __forceinline__ void mbar_init(unsigned mbar, unsigned count) {
    asm volatile("mbarrier.init.shared.b64 [%0], %1;" :: "r"(mbar), "r"(count) : "memory");
}

// expect_tx + TMA bulk copy global->shared, completion on mbarrier
__device__ __forceinline__ void bulk_ld(unsigned dst, const void* src,
                                        unsigned bytes, unsigned mbar) {
    asm volatile("mbarrier.arrive.expect_tx.shared.b64 _, [%0], %1;"
                 :: "r"(mbar), "r"(bytes) : "memory");
    asm volatile("cp.async.bulk.shared::cluster.global.mbarrier::complete_tx::bytes "
                 "[%0], [%1], %2, [%3];"
                 :: "r"(dst), "l"(src), "r"(bytes), "r"(mbar) : "memory");
}

__device__ __forceinline__ void mbar_wait(unsigned mbar, unsigned phase) {
    asm volatile(
        "{\n\t"
        ".reg .pred P;\n\t"
        "WAIT_%=:\n\t"
        "mbarrier.try_wait.parity.acquire.cta.shared::cta.b64 P, [%0], %1;\n\t"
        "@!P bra WAIT_%=;\n\t"
        "}"
        :: "r"(mbar), "r"(phase) : "memory");
}

__global__ void __launch_bounds__(THREADS) yolo_loss_kernel(
    const float* __restrict__ pred, const float* __restrict__ label,
    const float* __restrict__ anchors, float* __restrict__ out)
{
    __shared__ __align__(128) float s_tile[DEPTH][TILE_FLOATS];   // 2 x 20KB
    __shared__ float2 s_anch2[NA];             // squared anchors
    __shared__ float s_red[16];
    __shared__ unsigned s_flag;
    __shared__ __align__(8) unsigned long long s_mbar[DEPTH];

    const int tid = threadIdx.x;
    const int bid = blockIdx.x;
    if (tid < NA) {
        const float aw = anchors[2 * tid], ah = anchors[2 * tid + 1];
        s_anch2[tid] = make_float2(aw * aw, ah * ah);
    }
    if (tid == 0) {
#pragma unroll
        for (int s = 0; s < DEPTH; s++) mbar_init(smem_u32(&s_mbar[s]), 1);
    }
    __syncthreads();

    const char* __restrict__ pbytes = (const char*)pred;

    // ---- prologue: issue DEPTH bulk copies ----
    if (tid == 0) {
#pragma unroll
        for (int s = 0; s < DEPTH; s++) {
            const int t = bid + s * NBLOCKS;
            bulk_ld(smem_u32(s_tile[s]), pbytes + (long)t * TILE_BYTES,
                    TILE_BYTES, smem_u32(&s_mbar[s]));
        }
    }

    // ---- overlapped obj part: blocks 0..255 handle one sample each (thread 0) ----
    // Runs while the first TMA tile is in flight; latency fully hidden.
    if (bid < NB && tid == 0) {
        const int b = bid;
        const float lx = label[4 * b + 0];
        const float ly = label[4 * b + 1];
        const float lw = label[4 * b + 2];
        const float lh = label[4 * b + 3];

        const float fx = floorf(lx * (float)GW);
        const float fy = floorf(ly * (float)GH);
        const int idx = (int)(fx * (float)GH + fy);

        float best = -1.0f;
        int am = 0;
#pragma unroll
        for (int a = 0; a < NA; a++) {
            const float dw = lw - anchors[2 * a];
            const float dh = lh - anchors[2 * a + 1];
            const float d = dw * dw + dh * dh;
            if (d > best) { best = d; am = a; }   // first-max, matches argmax
        }
        const float aw = anchors[2 * am];
        const float ah = anchors[2 * am + 1];

        const float* p = pred + (((size_t)b * GRID_CELLS + (size_t)idx) * NA + (size_t)am) * 5;
        const float s0 = 1.0f / (1.0f + expf(-p[0]));
        const float s1 = 1.0f / (1.0f + expf(-p[1]));
        const float x = (s0 + fx) / (float)GW;
        const float y = (s1 + fy) / (float)GH;
        const float w = aw * expf(p[2]);
        const float h = ah * expf(p[3]);
        const float cf = 1.0f / (1.0f + expf(-p[4]));

        const float agx = (fx + 0.5f) / (float)GW;
        const float agy = (fy + 0.5f) / (float)GH;

        float t0 = x - agx, t1 = y - agy, t2 = w - aw, t3 = h - ah;
        const float coor_sq_obj = t0 * t0 + t1 * t1 + t2 * t2 + t3 * t3;
        const float conf_sq_obj = cf * cf;

        t0 = x - lx; t1 = y - ly; t2 = w - lw; t3 = h - lh;
        const float coor_obj = t0 * t0 + t1 * t1 + t2 * t2 + t3 * t3;

        // IoU (faithful to reference, incl. area = x2*y2 quirk)
        const float lx1 = fmaxf(lx - lw * 0.5f, 0.0f);
        const float ly1 = fmaxf(ly - lh * 0.5f, 0.0f);
        const float lx2 = fminf(lx + lw * 0.5f, 1.0f);
        const float ly2 = fminf(ly + lh * 0.5f, 1.0f);
        const float px1 = fmaxf(x - w * 0.5f, 0.0f);
        const float py1 = fmaxf(y - h * 0.5f, 0.0f);
        const float px2 = fminf(x + w * 0.5f, 1.0f);
        const float py2 = fminf(y + h * 0.5f, 1.0f);

        const float ix1 = fmaxf(lx1, px1);
        const float iy1 = fmaxf(ly1, py1);
        const float ix2 = fminf(lx2, px2);
        const float iy2 = fminf(ly2, py2);

        const float la = lx2 * ly2;
        const float pa = px2 * py2;
        const float inter = fmaxf(ix2 - ix1, 0.0f) * fmaxf(iy2 - iy1, 0.0f);
        const float iou = inter / (la + pa - inter);
        const float dcf = cf - iou;
        const float conf_obj = dcf * dcf;

        g_obj[b] = make_float4(coor_obj, conf_obj, coor_sq_obj, conf_sq_obj);
    }

    // raw accumulators (scaling deferred)
    float acc_xy = 0.0f;   // sum tanh^2 for x,y
    float acc_wh = 0.0f;   // sum a^2*(e-1)^2
    float acc_t  = 0.0f;   // sum tanh(conf/2)
    float acc_t2 = 0.0f;   // sum tanh(conf/2)^2

    // anchor index of element (t*1024 + tid): 1024%9==7 -> init (bid*7+tid)%9
    // per-tile step (t += 608): 608*1024 % 9 == 8 ; per k-chunk (+256): +4
    int a0 = (bid * 7 + tid) % 9;

    int stage = 0, phase = 0;
    for (int t = bid; t < NUM_TILES; t += NBLOCKS) {
        mbar_wait(smem_u32(&s_mbar[stage]), (unsigned)phase);

        const float* __restrict__ buf = s_tile[stage];
        int a = a0;
#pragma unroll
        for (int k = 0; k < 4; k++) {
            const int local = tid + k * THREADS;
            const float v0 = buf[5 * local + 0];
            const float v1 = buf[5 * local + 1];
            const float v2 = buf[5 * local + 2];
            const float v3 = buf[5 * local + 3];
            const float v4 = buf[5 * local + 4];
            const float2 a2 = s_anch2[a];

            const float tx = tanh_approx(0.5f * v0);
            const float ty = tanh_approx(0.5f * v1);
            acc_xy = fmaf(tx, tx, acc_xy);
            acc_xy = fmaf(ty, ty, acc_xy);

            const float ew = __expf(v2) - 1.0f;
            const float eh = __expf(v3) - 1.0f;
            acc_wh = fmaf(a2.x, ew * ew, acc_wh);
            acc_wh = fmaf(a2.y, eh * eh, acc_wh);

            const float tc = tanh_approx(0.5f * v4);
            acc_t += tc;
            acc_t2 = fmaf(tc, tc, acc_t2);

            a += 4; if (a >= 9) a -= 9;
        }

        __syncthreads();   // all threads done reading buf[stage]
        if (tid == 0) {
            const int tn = t + DEPTH * NBLOCKS;
            if (tn < NUM_TILES)
                bulk_ld(smem_u32(s_tile[stage]), pbytes + (long)tn * TILE_BYTES,
                        TILE_BYTES, smem_u32(&s_mbar[stage]));
        }

        stage ^= 1;
        phase ^= stage ^ 1;   // flip phase after stage wraps 1->0
        a0 += 8; if (a0 >= 9) a0 -= 9;
    }

    // per-thread element count for the deferred conf constant
    const int n_tiles = (NUM_TILES - 1 - bid) / NBLOCKS + 1;
    const float cnt = 4.0f * (float)n_tiles;

    // fold deferred scalings:  (sig-0.5)^2 = tanh^2/4 ; /(52^2) => /10816
    float coor = acc_wh + acc_xy * (1.0f / 10816.0f);
    // sig^2 = 0.25 + 0.5 t + 0.25 t^2
    float conf = 0.25f * cnt + 0.5f * acc_t + 0.25f * acc_t2;

    // ---- block reduction ----
    coor = warp_reduce(coor);
    conf = warp_reduce(conf);
    const int wid = tid >> 5, lid = tid & 31;
    if (lid == 0) { s_red[wid] = coor; s_red[8 + wid] = conf; }
    __syncthreads();
    if (wid == 0) {
        float c = (lid < 8) ? s_red[lid] : 0.0f;
        float f = (lid < 8) ? s_red[8 + lid] : 0.0f;
        c = warp_reduce(c);
        f = warp_reduce(f);
        if (lid == 0) {
            g_partials[bid] = make_float2(c, f);
            __threadfence();   // orders g_partials AND g_obj before the count bump
            const unsigned old = atomicAdd(&g_count, 1u);
            s_flag = (old == (unsigned)(NBLOCKS - 1)) ? 1u : 0u;
        }
    }
    __syncthreads();
    if (!s_flag) return;

    // ================= finishing block: combine everything =================
    const int b = tid;

    // noobj partials: indices b, b+256, (b+512 if b<96)
    double coorAll = 0.0, confAll = 0.0;
    {
        float2 v = g_partials[b];
        coorAll += (double)v.x; confAll += (double)v.y;
        v = g_partials[b + 256];
        coorAll += (double)v.x; confAll += (double)v.y;
        if (b < NBLOCKS - 512) {
            v = g_partials[b + 512];
            coorAll += (double)v.x; confAll += (double)v.y;
        }
    }
    const float4 ob = g_obj[b];   // (coor_obj, conf_obj, coor_sq_obj, conf_sq_obj)

    // reduce 6 quantities in shared (reuse tile buffer as scratch)
    double* red = (double*)s_tile;
    red[b * 6 + 0] = coorAll;
    red[b * 6 + 1] = confAll;
    red[b * 6 + 2] = (double)ob.z;
    red[b * 6 + 3] = (double)ob.w;
    red[b * 6 + 4] = (double)ob.x;
    red[b * 6 + 5] = (double)ob.y;
    __syncthreads();
    for (int s = THREADS / 2; s > 0; s >>= 1) {
        if (b < s) {
#pragma unroll
            for (int j = 0; j < 6; j++) red[b * 6 + j] += red[(b + s) * 6 + j];
        }
        __syncthreads();
    }

    if (b == 0) {
        const double GA1 = (double)(GRID_CELLS * NA - 1);   // 24335
        const double Bd = (double)NB;
        const double coor_l_noobj = (red[0] - red[2]) / (Bd * GA1 * 4.0);
        const double conf_l_noobj = (red[1] - red[3]) / (Bd * GA1);
        const double coor_l_obj = red[4] / (Bd * 4.0);
        const double conf_l_obj = red[5] / Bd;
        out[0] = (float)(coor_l_obj + coor_l_noobj + conf_l_obj + conf_l_noobj);
        g_count = 0;   // reset for next graph replay
    }
}

extern "C" void kernel_launch(void* const* d_in, const int* in_sizes, int n_in,
                              void* d_out, int out_size) {
    const float* pred    = (const float*)d_in[0];   // [256, 2704, 9, 5]
    const float* label   = (const float*)d_in[1];   // [256, 4]
    const float* anchors = (const float*)d_in[2];   // [9, 2]
    float* out = (float*)d_out;

    yolo_loss_kernel<<<NBLOCKS, THREADS>>>(pred, label, anchors, out);
}